// round 1
// baseline (speedup 1.0000x reference)
#include <cuda_runtime.h>
#include <cstdint>

#define DIN 128
#define DH  128
#define DOUT 64
#define NMAX 100000

// Scratch (allocation-free rule: __device__ globals)
__device__ float g_h1[(size_t)NMAX * DH];     // x @ W1
__device__ float g_a1[(size_t)NMAX * DH];     // aggregated layer-1 (pre bias/relu)
__device__ float g_h2[(size_t)NMAX * DOUT];   // relu(a1+b1) @ W2
__device__ float g_deg[NMAX];
__device__ float g_dinv[NMAX];

// ---------------------------------------------------------------- degrees
__global__ void k_deg_init(int n) {
    int i = blockIdx.x * blockDim.x + threadIdx.x;
    if (i < n) g_deg[i] = 1.0f;   // self-loop
}

__global__ void k_deg_count(const int* __restrict__ dst, int E) {
    int e = blockIdx.x * blockDim.x + threadIdx.x;
    if (e < E) atomicAdd(&g_deg[dst[e]], 1.0f);
}

__global__ void k_dinv(int n) {
    int i = blockIdx.x * blockDim.x + threadIdx.x;
    if (i < n) g_dinv[i] = rsqrtf(g_deg[i]);
}

// ---------------------------------------------------------------- GEMM1
// h1 = x @ W1 ; a1 = h1 * dinv^2  (self-loop init of the aggregation)
// Tile: 64 rows x 128 cols. block(32,8)=256 thr; thread: 8 rows x 4 cols.
// Smem: W1 full (64KB) + X tile (32KB) = 96KB dynamic.
__global__ void __launch_bounds__(256) k_gemm1(const float* __restrict__ x,
                                               const float* __restrict__ W1,
                                               int n) {
    extern __shared__ float sm[];
    float*  Ws  = sm;                 // [128][128]
    float*  Xs  = sm + DIN * DH;      // [64][128]
    float4* Ws4 = (float4*)Ws;
    float4* Xs4 = (float4*)Xs;

    const int tid = threadIdx.x;
    const int tx  = tid & 31;         // col float4 index (cols tx*4..tx*4+3)
    const int ty  = tid >> 5;         // row group (8 rows each)
    const int row0 = blockIdx.x * 64;

    // load W1 (16384 floats = 4096 float4)
    const float4* W4 = (const float4*)W1;
#pragma unroll
    for (int i = 0; i < 16; i++) Ws4[tid + 256 * i] = W4[tid + 256 * i];

    // load X tile (64x128 = 2048 float4), rows >= n -> 0
    const float4* x4 = (const float4*)x;
#pragma unroll
    for (int i = 0; i < 8; i++) {
        int idx = tid + 256 * i;
        int r = idx >> 5;             // 32 float4 per row
        float4 v = make_float4(0.f, 0.f, 0.f, 0.f);
        if (row0 + r < n) v = x4[(size_t)(row0 + r) * 32 + (idx & 31)];
        Xs4[idx] = v;
    }
    __syncthreads();

    float acc[8][4];
#pragma unroll
    for (int i = 0; i < 8; i++)
#pragma unroll
        for (int j = 0; j < 4; j++) acc[i][j] = 0.f;

    const int rbase = ty * 8;
#pragma unroll 4
    for (int k4 = 0; k4 < 32; k4++) {
        float4 b0 = Ws4[(4 * k4 + 0) * 32 + tx];
        float4 b1 = Ws4[(4 * k4 + 1) * 32 + tx];
        float4 b2 = Ws4[(4 * k4 + 2) * 32 + tx];
        float4 b3 = Ws4[(4 * k4 + 3) * 32 + tx];
#pragma unroll
        for (int i = 0; i < 8; i++) {
            float4 a = Xs4[(rbase + i) * 32 + k4];  // broadcast within warp
            acc[i][0] = fmaf(a.x, b0.x, fmaf(a.y, b1.x, fmaf(a.z, b2.x, fmaf(a.w, b3.x, acc[i][0]))));
            acc[i][1] = fmaf(a.x, b0.y, fmaf(a.y, b1.y, fmaf(a.z, b2.y, fmaf(a.w, b3.y, acc[i][1]))));
            acc[i][2] = fmaf(a.x, b0.z, fmaf(a.y, b1.z, fmaf(a.z, b2.z, fmaf(a.w, b3.z, acc[i][2]))));
            acc[i][3] = fmaf(a.x, b0.w, fmaf(a.y, b1.w, fmaf(a.z, b2.w, fmaf(a.w, b3.w, acc[i][3]))));
        }
    }

#pragma unroll
    for (int i = 0; i < 8; i++) {
        int r = row0 + rbase + i;
        if (r < n) {
            float di = g_dinv[r];
            float s = di * di;
            float4 h = make_float4(acc[i][0], acc[i][1], acc[i][2], acc[i][3]);
            ((float4*)g_h1)[(size_t)r * 32 + tx] = h;
            float4 a1v = make_float4(h.x * s, h.y * s, h.z * s, h.w * s);
            ((float4*)g_a1)[(size_t)r * 32 + tx] = a1v;
        }
    }
}

// ---------------------------------------------------------------- scatter layer 1
// One warp per edge: a1[dst] += h1[src] * dinv[src]*dinv[dst]
__global__ void __launch_bounds__(256) k_scatter1(const int* __restrict__ src,
                                                  const int* __restrict__ dst,
                                                  int E) {
    int w = (blockIdx.x * 256 + threadIdx.x) >> 5;
    if (w >= E) return;
    int lane = threadIdx.x & 31;
    int s = __ldg(&src[w]);
    int d = __ldg(&dst[w]);
    float nw = g_dinv[s] * g_dinv[d];
    float4 v = ((const float4*)g_h1)[(size_t)s * 32 + lane];
    float* p = g_a1 + (size_t)d * 128 + lane * 4;
    asm volatile("red.global.add.v4.f32 [%0], {%1, %2, %3, %4};"
                 :: "l"(p), "f"(v.x * nw), "f"(v.y * nw), "f"(v.z * nw), "f"(v.w * nw)
                 : "memory");
}

// ---------------------------------------------------------------- GEMM2
// h2 = relu(a1 + b1) @ W2 ; out = h2 * dinv^2 + b2   (self-loop init + bias)
// Tile: 64 rows x 64 cols. block 256: tx=tid&15 (col f4), ty=tid>>4 (4 rows each)
// Smem: W2 (32KB) + X tile (32KB) = 64KB dynamic.
__global__ void __launch_bounds__(256) k_gemm2(const float* __restrict__ W2,
                                               const float* __restrict__ b1,
                                               const float* __restrict__ b2,
                                               float* __restrict__ out,
                                               int n) {
    extern __shared__ float sm[];
    float*  Ws  = sm;               // [128][64]
    float*  Xs  = sm + DH * DOUT;   // [64][128]
    float4* Ws4 = (float4*)Ws;
    float4* Xs4 = (float4*)Xs;

    const int tid = threadIdx.x;
    const int tx  = tid & 15;       // col float4 index
    const int ty  = tid >> 4;       // row group (4 rows each)
    const int row0 = blockIdx.x * 64;

    // load W2 (8192 floats = 2048 float4)
    const float4* W4 = (const float4*)W2;
#pragma unroll
    for (int i = 0; i < 8; i++) Ws4[tid + 256 * i] = W4[tid + 256 * i];

    // load X tile = relu(a1 + b1), 2048 float4
    const float4* a14 = (const float4*)g_a1;
    const float4* b14 = (const float4*)b1;
#pragma unroll
    for (int i = 0; i < 8; i++) {
        int idx = tid + 256 * i;
        int r = idx >> 5;
        float4 v = make_float4(0.f, 0.f, 0.f, 0.f);
        if (row0 + r < n) {
            float4 av = a14[(size_t)(row0 + r) * 32 + (idx & 31)];
            float4 bv = __ldg(&b14[idx & 31]);
            v.x = fmaxf(av.x + bv.x, 0.f);
            v.y = fmaxf(av.y + bv.y, 0.f);
            v.z = fmaxf(av.z + bv.z, 0.f);
            v.w = fmaxf(av.w + bv.w, 0.f);
        }
        Xs4[idx] = v;
    }
    __syncthreads();

    float acc[4][4];
#pragma unroll
    for (int i = 0; i < 4; i++)
#pragma unroll
        for (int j = 0; j < 4; j++) acc[i][j] = 0.f;

    const int rbase = ty * 4;
#pragma unroll 4
    for (int k4 = 0; k4 < 32; k4++) {
        float4 b0 = Ws4[(4 * k4 + 0) * 16 + tx];
        float4 b1v = Ws4[(4 * k4 + 1) * 16 + tx];
        float4 b2v = Ws4[(4 * k4 + 2) * 16 + tx];
        float4 b3v = Ws4[(4 * k4 + 3) * 16 + tx];
#pragma unroll
        for (int i = 0; i < 4; i++) {
            float4 a = Xs4[(rbase + i) * 32 + k4];
            acc[i][0] = fmaf(a.x, b0.x, fmaf(a.y, b1v.x, fmaf(a.z, b2v.x, fmaf(a.w, b3v.x, acc[i][0]))));
            acc[i][1] = fmaf(a.x, b0.y, fmaf(a.y, b1v.y, fmaf(a.z, b2v.y, fmaf(a.w, b3v.y, acc[i][1]))));
            acc[i][2] = fmaf(a.x, b0.z, fmaf(a.y, b1v.z, fmaf(a.z, b2v.z, fmaf(a.w, b3v.z, acc[i][2]))));
            acc[i][3] = fmaf(a.x, b0.w, fmaf(a.y, b1v.w, fmaf(a.z, b2v.w, fmaf(a.w, b3v.w, acc[i][3]))));
        }
    }

    const float4* b24 = (const float4*)b2;
    float4 bb = __ldg(&b24[tx]);
#pragma unroll
    for (int i = 0; i < 4; i++) {
        int r = row0 + rbase + i;
        if (r < n) {
            float di = g_dinv[r];
            float s = di * di;
            float4 h = make_float4(acc[i][0], acc[i][1], acc[i][2], acc[i][3]);
            ((float4*)g_h2)[(size_t)r * 16 + tx] = h;
            float4 o = make_float4(h.x * s + bb.x, h.y * s + bb.y,
                                   h.z * s + bb.z, h.w * s + bb.w);
            ((float4*)out)[(size_t)r * 16 + tx] = o;
        }
    }
}

// ---------------------------------------------------------------- scatter layer 2
// Half-warp per edge: out[dst] += h2[src] * dinv[src]*dinv[dst]   (64 floats)
__global__ void __launch_bounds__(256) k_scatter2(const int* __restrict__ src,
                                                  const int* __restrict__ dst,
                                                  float* __restrict__ out,
                                                  int E) {
    int hw = (blockIdx.x * 256 + threadIdx.x) >> 4;
    if (hw >= E) return;
    int l = threadIdx.x & 15;
    int s = __ldg(&src[hw]);
    int d = __ldg(&dst[hw]);
    float nw = g_dinv[s] * g_dinv[d];
    float4 v = ((const float4*)g_h2)[(size_t)s * 16 + l];
    float* p = out + (size_t)d * 64 + l * 4;
    asm volatile("red.global.add.v4.f32 [%0], {%1, %2, %3, %4};"
                 :: "l"(p), "f"(v.x * nw), "f"(v.y * nw), "f"(v.z * nw), "f"(v.w * nw)
                 : "memory");
}

// ---------------------------------------------------------------- launch
extern "C" void kernel_launch(void* const* d_in, const int* in_sizes, int n_in,
                              void* d_out, int out_size) {
    const float* x  = (const float*)d_in[0];
    const int*   ei = (const int*)d_in[1];
    const float* W1 = (const float*)d_in[2];
    const float* b1 = (const float*)d_in[3];
    const float* W2 = (const float*)d_in[4];
    const float* b2 = (const float*)d_in[5];
    float* out = (float*)d_out;

    const int n = in_sizes[0] / DIN;
    const int E = in_sizes[1] / 2;
    const int* src = ei;        // edge_index row 0
    const int* dst = ei + E;    // edge_index row 1

    const int SMEM1 = (DIN * DH + 64 * DIN) * (int)sizeof(float);    // 96 KB
    const int SMEM2 = (DH * DOUT + 64 * DH) * (int)sizeof(float);    // 64 KB
    cudaFuncSetAttribute(k_gemm1, cudaFuncAttributeMaxDynamicSharedMemorySize, SMEM1);
    cudaFuncSetAttribute(k_gemm2, cudaFuncAttributeMaxDynamicSharedMemorySize, SMEM2);

    k_deg_init<<<(n + 255) / 256, 256>>>(n);
    k_deg_count<<<(E + 255) / 256, 256>>>(dst, E);
    k_dinv<<<(n + 255) / 256, 256>>>(n);

    k_gemm1<<<(n + 63) / 64, 256, SMEM1>>>(x, W1, n);
    k_scatter1<<<(E + 7) / 8, 256>>>(src, dst, E);

    k_gemm2<<<(n + 63) / 64, 256, SMEM2>>>(W2, b1, b2, out, n);
    k_scatter2<<<(E + 15) / 16, 256>>>(src, dst, out, E);
}

// round 2
// speedup vs baseline: 1.4926x; 1.4926x over previous
#include <cuda_runtime.h>
#include <cstdint>

#define DIN 128
#define DH  128
#define DOUT 64
#define NMAX 100000
#define EMAX 1600000

// ---------------------------------------------------------------- scratch
__device__ float g_hs1[(size_t)NMAX * DH];    // (x@W1) * dinv[row]
__device__ float g_a1[(size_t)NMAX * DH];     // aggregated layer-1 (pre bias/relu)
__device__ float g_hs2[(size_t)NMAX * DOUT];  // (relu(a1+b1)@W2) * dinv[row]
__device__ float g_dinv[NMAX];
__device__ int   g_cnt[NMAX];                 // in-degree (without self loop)
__device__ int   g_rowstart[NMAX];            // CSR row offsets (exclusive scan of cnt)
__device__ int   g_cursor[NMAX];
__device__ int   g_csrc[EMAX];                // src indices grouped by dst
__device__ int   g_bsum[128];                 // scan block sums
__device__ int   g_bpre[128];

// ---------------------------------------------------------------- degree / CSR build
__global__ void k_zero_cnt(int n) {
    int i = blockIdx.x * blockDim.x + threadIdx.x;
    if (i < n) g_cnt[i] = 0;
}

__global__ void k_count(const int* __restrict__ dst, int E) {
    int e = blockIdx.x * blockDim.x + threadIdx.x;
    if (e < E) atomicAdd(&g_cnt[dst[e]], 1);
}

__global__ void k_dinv(int n) {
    int i = blockIdx.x * blockDim.x + threadIdx.x;
    if (i < n) g_dinv[i] = rsqrtf(1.0f + (float)g_cnt[i]);   // +1 self loop
}

// block-wise exclusive scan (1024/block) -> rowstart holds local exclusive, bsum[b]=total
__global__ void __launch_bounds__(1024) k_scan1(int n) {
    __shared__ int sm[1024];
    int i = blockIdx.x * 1024 + threadIdx.x;
    int v = (i < n) ? g_cnt[i] : 0;
    sm[threadIdx.x] = v;
    __syncthreads();
#pragma unroll
    for (int off = 1; off < 1024; off <<= 1) {
        int t = (threadIdx.x >= off) ? sm[threadIdx.x - off] : 0;
        __syncthreads();
        sm[threadIdx.x] += t;
        __syncthreads();
    }
    int inc = sm[threadIdx.x];
    if (i < n) g_rowstart[i] = inc - v;
    if (threadIdx.x == 1023) g_bsum[blockIdx.x] = inc;
}

// scan of block sums (<=128)
__global__ void __launch_bounds__(128) k_scan2(int nb) {
    __shared__ int sm[128];
    int v = (threadIdx.x < nb) ? g_bsum[threadIdx.x] : 0;
    sm[threadIdx.x] = v;
    __syncthreads();
#pragma unroll
    for (int off = 1; off < 128; off <<= 1) {
        int t = (threadIdx.x >= off) ? sm[threadIdx.x - off] : 0;
        __syncthreads();
        sm[threadIdx.x] += t;
        __syncthreads();
    }
    g_bpre[threadIdx.x] = sm[threadIdx.x] - v;
}

__global__ void k_scan3(int n) {
    int i = blockIdx.x * blockDim.x + threadIdx.x;
    if (i < n) {
        int rs = g_rowstart[i] + g_bpre[i >> 10];
        g_rowstart[i] = rs;
        g_cursor[i] = rs;
    }
}

__global__ void k_fill(const int* __restrict__ src, const int* __restrict__ dst, int E) {
    int e = blockIdx.x * blockDim.x + threadIdx.x;
    if (e < E) {
        int p = atomicAdd(&g_cursor[dst[e]], 1);
        g_csrc[p] = src[e];
    }
}

// ---------------------------------------------------------------- GEMM1
// hs1 = (x @ W1) * dinv[row].  Tile 128x128, 256 thr, thread = 16 rows x 4 cols.
__global__ void __launch_bounds__(256) k_gemm1(const float* __restrict__ x,
                                               const float* __restrict__ W1,
                                               int n) {
    extern __shared__ float sm[];
    float4* Ws4 = (float4*)sm;                  // [128][32] f4
    float4* Xs4 = (float4*)(sm + DIN * DH);     // [128][32] f4

    const int tid = threadIdx.x;
    const int tx  = tid & 31;                   // col f4
    const int ty  = tid >> 5;                   // 0..7, 16 rows each
    const int row0 = blockIdx.x * 128;

    const float4* W4 = (const float4*)W1;
#pragma unroll
    for (int i = 0; i < 16; i++) Ws4[tid + 256 * i] = W4[tid + 256 * i];

    const float4* x4 = (const float4*)x;
#pragma unroll
    for (int i = 0; i < 16; i++) {
        int idx = tid + 256 * i;
        int r = idx >> 5;
        float4 v = make_float4(0.f, 0.f, 0.f, 0.f);
        if (row0 + r < n) v = x4[(size_t)(row0 + r) * 32 + (idx & 31)];
        Xs4[idx] = v;
    }
    __syncthreads();

    float acc[16][4];
#pragma unroll
    for (int i = 0; i < 16; i++)
#pragma unroll
        for (int j = 0; j < 4; j++) acc[i][j] = 0.f;

    const int rbase = ty * 16;
#pragma unroll 2
    for (int k4 = 0; k4 < 32; k4++) {
        float4 b0 = Ws4[(4 * k4 + 0) * 32 + tx];
        float4 b1 = Ws4[(4 * k4 + 1) * 32 + tx];
        float4 b2 = Ws4[(4 * k4 + 2) * 32 + tx];
        float4 b3 = Ws4[(4 * k4 + 3) * 32 + tx];
#pragma unroll
        for (int i = 0; i < 16; i++) {
            float4 a = Xs4[(rbase + i) * 32 + k4];
            acc[i][0] = fmaf(a.x, b0.x, fmaf(a.y, b1.x, fmaf(a.z, b2.x, fmaf(a.w, b3.x, acc[i][0]))));
            acc[i][1] = fmaf(a.x, b0.y, fmaf(a.y, b1.y, fmaf(a.z, b2.y, fmaf(a.w, b3.y, acc[i][1]))));
            acc[i][2] = fmaf(a.x, b0.z, fmaf(a.y, b1.z, fmaf(a.z, b2.z, fmaf(a.w, b3.z, acc[i][2]))));
            acc[i][3] = fmaf(a.x, b0.w, fmaf(a.y, b1.w, fmaf(a.z, b2.w, fmaf(a.w, b3.w, acc[i][3]))));
        }
    }

#pragma unroll
    for (int i = 0; i < 16; i++) {
        int r = row0 + rbase + i;
        if (r < n) {
            float dv = g_dinv[r];
            float4 h = make_float4(acc[i][0] * dv, acc[i][1] * dv,
                                   acc[i][2] * dv, acc[i][3] * dv);
            ((float4*)g_hs1)[(size_t)r * 32 + tx] = h;
        }
    }
}

// ---------------------------------------------------------------- agg layer 1
// a1[d] = dinv[d] * (hs1[d] + sum_{s in N(d)} hs1[s]).  Warp per node.
__global__ void __launch_bounds__(256) k_agg1(int n) {
    int w = (blockIdx.x * 256 + threadIdx.x) >> 5;
    if (w >= n) return;
    int lane = threadIdx.x & 31;
    const float4* hs = (const float4*)g_hs1;

    float4 acc = hs[(size_t)w * 32 + lane];          // self loop
    int start = g_rowstart[w];
    int end = start + g_cnt[w];

    for (int base = start; base < end; base += 32) {
        int idx = base + lane;
        int s = (idx < end) ? __ldg(&g_csrc[idx]) : 0;
        int m = min(32, end - base);
        for (int k = 0; k < m; k++) {
            int ss = __shfl_sync(0xffffffffu, s, k);
            float4 v = hs[(size_t)ss * 32 + lane];
            acc.x += v.x; acc.y += v.y; acc.z += v.z; acc.w += v.w;
        }
    }
    float dv = g_dinv[w];
    float4 o = make_float4(acc.x * dv, acc.y * dv, acc.z * dv, acc.w * dv);
    ((float4*)g_a1)[(size_t)w * 32 + lane] = o;
}

// ---------------------------------------------------------------- GEMM2
// hs2 = (relu(a1+b1) @ W2) * dinv[row].  Tile 128x64, 256 thr, thread = 8 rows x 4 cols.
__global__ void __launch_bounds__(256) k_gemm2(const float* __restrict__ W2,
                                               const float* __restrict__ b1,
                                               int n) {
    extern __shared__ float sm[];
    float4* Ws4 = (float4*)sm;                   // [128][16] f4
    float4* Xs4 = (float4*)(sm + DH * DOUT);     // [128][32] f4

    const int tid = threadIdx.x;
    const int tx  = tid & 15;                    // col f4
    const int ty  = tid >> 4;                    // 0..15, 8 rows each
    const int row0 = blockIdx.x * 128;

    const float4* W4 = (const float4*)W2;
#pragma unroll
    for (int i = 0; i < 8; i++) Ws4[tid + 256 * i] = W4[tid + 256 * i];

    const float4* a14 = (const float4*)g_a1;
    const float4* b14 = (const float4*)b1;
#pragma unroll
    for (int i = 0; i < 16; i++) {
        int idx = tid + 256 * i;
        int r = idx >> 5;
        float4 v = make_float4(0.f, 0.f, 0.f, 0.f);
        if (row0 + r < n) {
            float4 av = a14[(size_t)(row0 + r) * 32 + (idx & 31)];
            float4 bv = __ldg(&b14[idx & 31]);
            v.x = fmaxf(av.x + bv.x, 0.f);
            v.y = fmaxf(av.y + bv.y, 0.f);
            v.z = fmaxf(av.z + bv.z, 0.f);
            v.w = fmaxf(av.w + bv.w, 0.f);
        }
        Xs4[idx] = v;
    }
    __syncthreads();

    float acc[8][4];
#pragma unroll
    for (int i = 0; i < 8; i++)
#pragma unroll
        for (int j = 0; j < 4; j++) acc[i][j] = 0.f;

    const int rbase = ty * 8;
#pragma unroll 4
    for (int k4 = 0; k4 < 32; k4++) {
        float4 c0 = Ws4[(4 * k4 + 0) * 16 + tx];
        float4 c1 = Ws4[(4 * k4 + 1) * 16 + tx];
        float4 c2 = Ws4[(4 * k4 + 2) * 16 + tx];
        float4 c3 = Ws4[(4 * k4 + 3) * 16 + tx];
#pragma unroll
        for (int i = 0; i < 8; i++) {
            float4 a = Xs4[(rbase + i) * 32 + k4];
            acc[i][0] = fmaf(a.x, c0.x, fmaf(a.y, c1.x, fmaf(a.z, c2.x, fmaf(a.w, c3.x, acc[i][0]))));
            acc[i][1] = fmaf(a.x, c0.y, fmaf(a.y, c1.y, fmaf(a.z, c2.y, fmaf(a.w, c3.y, acc[i][1]))));
            acc[i][2] = fmaf(a.x, c0.z, fmaf(a.y, c1.z, fmaf(a.z, c2.z, fmaf(a.w, c3.z, acc[i][2]))));
            acc[i][3] = fmaf(a.x, c0.w, fmaf(a.y, c1.w, fmaf(a.z, c2.w, fmaf(a.w, c3.w, acc[i][3]))));
        }
    }

#pragma unroll
    for (int i = 0; i < 8; i++) {
        int r = row0 + rbase + i;
        if (r < n) {
            float dv = g_dinv[r];
            float4 h = make_float4(acc[i][0] * dv, acc[i][1] * dv,
                                   acc[i][2] * dv, acc[i][3] * dv);
            ((float4*)g_hs2)[(size_t)r * 16 + tx] = h;
        }
    }
}

// ---------------------------------------------------------------- agg layer 2
// out[d] = dinv[d] * (hs2[d] + sum hs2[s]) + b2.  Half-warp (16 lanes) per node.
__global__ void __launch_bounds__(256) k_agg2(const float* __restrict__ b2,
                                              float* __restrict__ out, int n) {
    int g = (blockIdx.x * 256 + threadIdx.x) >> 4;
    if (g >= n) return;
    int l = threadIdx.x & 15;
    unsigned mask = (threadIdx.x & 16) ? 0xffff0000u : 0x0000ffffu;
    const float4* hs = (const float4*)g_hs2;

    float4 acc = hs[(size_t)g * 16 + l];             // self loop
    int start = g_rowstart[g];
    int end = start + g_cnt[g];

    for (int base = start; base < end; base += 16) {
        int idx = base + l;
        int s = (idx < end) ? __ldg(&g_csrc[idx]) : 0;
        int m = min(16, end - base);
        for (int k = 0; k < m; k++) {
            int ss = __shfl_sync(mask, s, k, 16);
            float4 v = hs[(size_t)ss * 16 + l];
            acc.x += v.x; acc.y += v.y; acc.z += v.z; acc.w += v.w;
        }
    }
    float dv = g_dinv[g];
    float4 bb = __ldg(&((const float4*)b2)[l]);
    float4 o = make_float4(acc.x * dv + bb.x, acc.y * dv + bb.y,
                           acc.z * dv + bb.z, acc.w * dv + bb.w);
    ((float4*)out)[(size_t)g * 16 + l] = o;
}

// ---------------------------------------------------------------- launch
extern "C" void kernel_launch(void* const* d_in, const int* in_sizes, int n_in,
                              void* d_out, int out_size) {
    const float* x  = (const float*)d_in[0];
    const int*   ei = (const int*)d_in[1];
    const float* W1 = (const float*)d_in[2];
    const float* b1 = (const float*)d_in[3];
    const float* W2 = (const float*)d_in[4];
    const float* b2 = (const float*)d_in[5];
    float* out = (float*)d_out;

    const int n = in_sizes[0] / DIN;
    const int E = in_sizes[1] / 2;
    const int* src = ei;
    const int* dst = ei + E;

    const int SMEM1 = (DIN * DH + 128 * DIN) * (int)sizeof(float);   // 128 KB
    const int SMEM2 = (DH * DOUT + 128 * DH) * (int)sizeof(float);   // 96 KB
    cudaFuncSetAttribute(k_gemm1, cudaFuncAttributeMaxDynamicSharedMemorySize, SMEM1);
    cudaFuncSetAttribute(k_gemm2, cudaFuncAttributeMaxDynamicSharedMemorySize, SMEM2);

    const int nb = (n + 1023) / 1024;

    // CSR build + degree norm
    k_zero_cnt<<<(n + 255) / 256, 256>>>(n);
    k_count<<<(E + 255) / 256, 256>>>(dst, E);
    k_dinv<<<(n + 255) / 256, 256>>>(n);
    k_scan1<<<nb, 1024>>>(n);
    k_scan2<<<1, 128>>>(nb);
    k_scan3<<<(n + 255) / 256, 256>>>(n);
    k_fill<<<(E + 255) / 256, 256>>>(src, dst, E);

    // layer 1
    k_gemm1<<<(n + 127) / 128, 256, SMEM1>>>(x, W1, n);
    k_agg1<<<(n * 32 + 255) / 256, 256>>>(n);

    // layer 2
    k_gemm2<<<(n + 127) / 128, 256, SMEM2>>>(W2, b1, n);
    k_agg2<<<(n * 16 + 255) / 256, 256>>>(b2, out, n);
}

// round 3
// speedup vs baseline: 2.0743x; 1.3897x over previous
#include <cuda_runtime.h>
#include <cuda_fp16.h>
#include <mma.h>
#include <cstdint>

using namespace nvcuda;

#define DIN 128
#define DH  128
#define DOUT 64
#define NMAX 100000
#define EMAX 1600000

// ---------------------------------------------------------------- scratch
__device__ __half g_hs1[(size_t)NMAX * DH];    // (x@W1) * dinv[row], fp16
__device__ float  g_a1[(size_t)NMAX * DH];     // aggregated layer-1 (pre bias/relu)
__device__ __half g_hs2[(size_t)NMAX * DOUT];  // (relu(a1+b1)@W2) * dinv[row], fp16
__device__ float  g_dinv[NMAX];
__device__ int    g_cnt[NMAX];
__device__ int    g_rowstart[NMAX];
__device__ int    g_cursor[NMAX];
__device__ int    g_csrc[EMAX];
__device__ int    g_bsum[128];
__device__ int    g_bpre[128];

// ---------------------------------------------------------------- degree / CSR build
__global__ void k_zero_cnt(int n) {
    int i = blockIdx.x * blockDim.x + threadIdx.x;
    if (i < n) g_cnt[i] = 0;
}

__global__ void k_count(const int* __restrict__ dst, int E) {
    int e = blockIdx.x * blockDim.x + threadIdx.x;
    if (e < E) atomicAdd(&g_cnt[dst[e]], 1);
}

__global__ void k_dinv(int n) {
    int i = blockIdx.x * blockDim.x + threadIdx.x;
    if (i < n) g_dinv[i] = rsqrtf(1.0f + (float)g_cnt[i]);
}

__global__ void __launch_bounds__(1024) k_scan1(int n) {
    __shared__ int sm[1024];
    int i = blockIdx.x * 1024 + threadIdx.x;
    int v = (i < n) ? g_cnt[i] : 0;
    sm[threadIdx.x] = v;
    __syncthreads();
#pragma unroll
    for (int off = 1; off < 1024; off <<= 1) {
        int t = (threadIdx.x >= off) ? sm[threadIdx.x - off] : 0;
        __syncthreads();
        sm[threadIdx.x] += t;
        __syncthreads();
    }
    int inc = sm[threadIdx.x];
    if (i < n) g_rowstart[i] = inc - v;
    if (threadIdx.x == 1023) g_bsum[blockIdx.x] = inc;
}

__global__ void __launch_bounds__(128) k_scan2(int nb) {
    __shared__ int sm[128];
    int v = (threadIdx.x < nb) ? g_bsum[threadIdx.x] : 0;
    sm[threadIdx.x] = v;
    __syncthreads();
#pragma unroll
    for (int off = 1; off < 128; off <<= 1) {
        int t = (threadIdx.x >= off) ? sm[threadIdx.x - off] : 0;
        __syncthreads();
        sm[threadIdx.x] += t;
        __syncthreads();
    }
    g_bpre[threadIdx.x] = sm[threadIdx.x] - v;
}

__global__ void k_scan3(int n) {
    int i = blockIdx.x * blockDim.x + threadIdx.x;
    if (i < n) {
        int rs = g_rowstart[i] + g_bpre[i >> 10];
        g_rowstart[i] = rs;
        g_cursor[i] = rs;
    }
}

__global__ void k_fill(const int* __restrict__ src, const int* __restrict__ dst, int E) {
    int e = blockIdx.x * blockDim.x + threadIdx.x;
    if (e < E) {
        int p = atomicAdd(&g_cursor[dst[e]], 1);
        g_csrc[p] = src[e];
    }
}

// ---------------------------------------------------------------- GEMM1 (wmma fp16)
// hs1 = (x @ W1) * dinv[row], output fp16.
// Block: 256 thr (8 warps), tile 128 rows x 128 cols.
// Warp (wid/2, wid%2): rows (wid>>1)*32, cols (wid&1)*64 -> 2x4 16x16 frags.
#define LDA 136   // half, padded
#define LDC 132   // float, padded
__global__ void __launch_bounds__(256) k_gemm1(const float* __restrict__ x,
                                               const float* __restrict__ W1,
                                               int n) {
    extern __shared__ char smraw[];
    __half* Ah = (__half*)smraw;                       // [128][136]
    __half* Bh = Ah + 128 * LDA;                       // [128][136]
    float*  Cf = (float*)(Bh + 128 * LDA);             // [128][132]

    const int tid = threadIdx.x;
    const int row0 = blockIdx.x * 128;

    // load A = x tile (fp32 -> fp16), 128x128 = 4096 float4
    const float4* x4 = (const float4*)x;
#pragma unroll
    for (int i = 0; i < 16; i++) {
        int idx = tid + 256 * i;
        int r = idx >> 5, c4 = idx & 31;
        float4 v = make_float4(0.f, 0.f, 0.f, 0.f);
        if (row0 + r < n) v = x4[(size_t)(row0 + r) * 32 + c4];
        __half2* p = (__half2*)&Ah[r * LDA + c4 * 4];
        p[0] = __floats2half2_rn(v.x, v.y);
        p[1] = __floats2half2_rn(v.z, v.w);
    }
    // load B = W1 (fp32 -> fp16)
    const float4* W4 = (const float4*)W1;
#pragma unroll
    for (int i = 0; i < 16; i++) {
        int idx = tid + 256 * i;
        int r = idx >> 5, c4 = idx & 31;
        float4 v = W4[idx];
        __half2* p = (__half2*)&Bh[r * LDA + c4 * 4];
        p[0] = __floats2half2_rn(v.x, v.y);
        p[1] = __floats2half2_rn(v.z, v.w);
    }
    __syncthreads();

    const int wid = tid >> 5;
    const int wr = (wid >> 1) * 32;
    const int wc = (wid & 1) * 64;

    wmma::fragment<wmma::accumulator, 16, 16, 16, float> cf[2][4];
#pragma unroll
    for (int i = 0; i < 2; i++)
#pragma unroll
        for (int j = 0; j < 4; j++) wmma::fill_fragment(cf[i][j], 0.f);

#pragma unroll
    for (int k = 0; k < 8; k++) {
        wmma::fragment<wmma::matrix_a, 16, 16, 16, __half, wmma::row_major> af[2];
#pragma unroll
        for (int i = 0; i < 2; i++)
            wmma::load_matrix_sync(af[i], &Ah[(wr + 16 * i) * LDA + 16 * k], LDA);
#pragma unroll
        for (int j = 0; j < 4; j++) {
            wmma::fragment<wmma::matrix_b, 16, 16, 16, __half, wmma::row_major> bf;
            wmma::load_matrix_sync(bf, &Bh[16 * k * LDA + wc + 16 * j], LDA);
#pragma unroll
            for (int i = 0; i < 2; i++)
                wmma::mma_sync(cf[i][j], af[i], bf, cf[i][j]);
        }
    }

#pragma unroll
    for (int i = 0; i < 2; i++)
#pragma unroll
        for (int j = 0; j < 4; j++)
            wmma::store_matrix_sync(&Cf[(wr + 16 * i) * LDC + wc + 16 * j],
                                    cf[i][j], LDC, wmma::mem_row_major);
    __syncthreads();

    // epilogue: scale by dinv, convert fp16, store
#pragma unroll
    for (int i = 0; i < 16; i++) {
        int idx = tid + 256 * i;
        int r = idx >> 5, c4 = idx & 31;
        int gr = row0 + r;
        if (gr < n) {
            float dv = g_dinv[gr];
            float* c = &Cf[r * LDC + c4 * 4];
            __half2 h0 = __floats2half2_rn(c[0] * dv, c[1] * dv);
            __half2 h1 = __floats2half2_rn(c[2] * dv, c[3] * dv);
            __half2* o = (__half2*)&g_hs1[(size_t)gr * DH + c4 * 4];
            o[0] = h0; o[1] = h1;
        }
    }
}

// ---------------------------------------------------------------- agg layer 1
// a1[d] = dinv[d] * (hs1[d] + sum_{s in N(d)} hs1[s]).  Warp per node, fp16 gather.
__global__ void __launch_bounds__(256) k_agg1(int n) {
    int w = (blockIdx.x * 256 + threadIdx.x) >> 5;
    if (w >= n) return;
    int lane = threadIdx.x & 31;
    const uint2* hs = (const uint2*)g_hs1;   // 4 halves per uint2, 32 per row

    uint2 sv = hs[(size_t)w * 32 + lane];
    __half2 a01 = *(__half2*)&sv.x, a23 = *(__half2*)&sv.y;
    float4 acc = make_float4(__low2float(a01), __high2float(a01),
                             __low2float(a23), __high2float(a23));

    int start = g_rowstart[w];
    int end = start + g_cnt[w];
    for (int base = start; base < end; base += 32) {
        int idx = base + lane;
        int s = (idx < end) ? __ldg(&g_csrc[idx]) : 0;
        int m = min(32, end - base);
        for (int k = 0; k < m; k++) {
            int ss = __shfl_sync(0xffffffffu, s, k);
            uint2 v = hs[(size_t)ss * 32 + lane];
            __half2 h01 = *(__half2*)&v.x, h23 = *(__half2*)&v.y;
            acc.x += __low2float(h01); acc.y += __high2float(h01);
            acc.z += __low2float(h23); acc.w += __high2float(h23);
        }
    }
    float dv = g_dinv[w];
    float4 o = make_float4(acc.x * dv, acc.y * dv, acc.z * dv, acc.w * dv);
    ((float4*)g_a1)[(size_t)w * 32 + lane] = o;
}

// ---------------------------------------------------------------- GEMM2 (wmma fp16)
// hs2 = (relu(a1+b1) @ W2) * dinv[row], output fp16.
// Tile 128 rows x 64 cols; 8 warps, each 16 rows x 64 cols -> 1x4 frags.
#define LDB2 72
#define LDC2 68
__global__ void __launch_bounds__(256) k_gemm2(const float* __restrict__ W2,
                                               const float* __restrict__ b1,
                                               int n) {
    extern __shared__ char smraw[];
    __half* Ah = (__half*)smraw;                       // [128][136]
    __half* Bh = Ah + 128 * LDA;                       // [128][72]
    float*  Cf = (float*)(Bh + 128 * LDB2);            // [128][68]

    const int tid = threadIdx.x;
    const int row0 = blockIdx.x * 128;

    // load A = relu(a1 + b1) (fp32 -> fp16)
    const float4* a14 = (const float4*)g_a1;
    const float4* b14 = (const float4*)b1;
#pragma unroll
    for (int i = 0; i < 16; i++) {
        int idx = tid + 256 * i;
        int r = idx >> 5, c4 = idx & 31;
        float4 v = make_float4(0.f, 0.f, 0.f, 0.f);
        if (row0 + r < n) {
            float4 av = a14[(size_t)(row0 + r) * 32 + c4];
            float4 bv = __ldg(&b14[c4]);
            v.x = fmaxf(av.x + bv.x, 0.f);
            v.y = fmaxf(av.y + bv.y, 0.f);
            v.z = fmaxf(av.z + bv.z, 0.f);
            v.w = fmaxf(av.w + bv.w, 0.f);
        }
        __half2* p = (__half2*)&Ah[r * LDA + c4 * 4];
        p[0] = __floats2half2_rn(v.x, v.y);
        p[1] = __floats2half2_rn(v.z, v.w);
    }
    // load B = W2 128x64 (fp32 -> fp16), 2048 float4
    const float4* W4 = (const float4*)W2;
#pragma unroll
    for (int i = 0; i < 8; i++) {
        int idx = tid + 256 * i;
        int r = idx >> 4, c4 = idx & 15;
        float4 v = W4[idx];
        __half2* p = (__half2*)&Bh[r * LDB2 + c4 * 4];
        p[0] = __floats2half2_rn(v.x, v.y);
        p[1] = __floats2half2_rn(v.z, v.w);
    }
    __syncthreads();

    const int wid = tid >> 5;
    const int wr = wid * 16;

    wmma::fragment<wmma::accumulator, 16, 16, 16, float> cf[4];
#pragma unroll
    for (int j = 0; j < 4; j++) wmma::fill_fragment(cf[j], 0.f);

#pragma unroll
    for (int k = 0; k < 8; k++) {
        wmma::fragment<wmma::matrix_a, 16, 16, 16, __half, wmma::row_major> af;
        wmma::load_matrix_sync(af, &Ah[wr * LDA + 16 * k], LDA);
#pragma unroll
        for (int j = 0; j < 4; j++) {
            wmma::fragment<wmma::matrix_b, 16, 16, 16, __half, wmma::row_major> bf;
            wmma::load_matrix_sync(bf, &Bh[16 * k * LDB2 + 16 * j], LDB2);
            wmma::mma_sync(cf[j], af, bf, cf[j]);
        }
    }

#pragma unroll
    for (int j = 0; j < 4; j++)
        wmma::store_matrix_sync(&Cf[wr * LDC2 + 16 * j], cf[j], LDC2,
                                wmma::mem_row_major);
    __syncthreads();

    // epilogue: scale by dinv, convert fp16. 128 rows x 16 f4 = 2048
#pragma unroll
    for (int i = 0; i < 8; i++) {
        int idx = tid + 256 * i;
        int r = idx >> 4, c4 = idx & 15;
        int gr = row0 + r;
        if (gr < n) {
            float dv = g_dinv[gr];
            float* c = &Cf[r * LDC2 + c4 * 4];
            __half2 h0 = __floats2half2_rn(c[0] * dv, c[1] * dv);
            __half2 h1 = __floats2half2_rn(c[2] * dv, c[3] * dv);
            __half2* o = (__half2*)&g_hs2[(size_t)gr * DOUT + c4 * 4];
            o[0] = h0; o[1] = h1;
        }
    }
}

// ---------------------------------------------------------------- agg layer 2
// out[d] = dinv[d] * (hs2[d] + sum hs2[s]) + b2.  Warp per node, 2 halves/lane.
__global__ void __launch_bounds__(256) k_agg2(const float* __restrict__ b2,
                                              float* __restrict__ out, int n) {
    int w = (blockIdx.x * 256 + threadIdx.x) >> 5;
    if (w >= n) return;
    int lane = threadIdx.x & 31;
    const unsigned* hs = (const unsigned*)g_hs2;   // 2 halves per uint, 32 per row

    unsigned sv = hs[(size_t)w * 32 + lane];
    __half2 sh = *(__half2*)&sv;
    float2 acc = make_float2(__low2float(sh), __high2float(sh));

    int start = g_rowstart[w];
    int end = start + g_cnt[w];
    for (int base = start; base < end; base += 32) {
        int idx = base + lane;
        int s = (idx < end) ? __ldg(&g_csrc[idx]) : 0;
        int m = min(32, end - base);
        for (int k = 0; k < m; k++) {
            int ss = __shfl_sync(0xffffffffu, s, k);
            unsigned v = hs[(size_t)ss * 32 + lane];
            __half2 h = *(__half2*)&v;
            acc.x += __low2float(h); acc.y += __high2float(h);
        }
    }
    float dv = g_dinv[w];
    float2 bb = __ldg(&((const float2*)b2)[lane]);
    float2 o = make_float2(acc.x * dv + bb.x, acc.y * dv + bb.y);
    ((float2*)out)[(size_t)w * 32 + lane] = o;
}

// ---------------------------------------------------------------- launch
extern "C" void kernel_launch(void* const* d_in, const int* in_sizes, int n_in,
                              void* d_out, int out_size) {
    const float* x  = (const float*)d_in[0];
    const int*   ei = (const int*)d_in[1];
    const float* W1 = (const float*)d_in[2];
    const float* b1 = (const float*)d_in[3];
    const float* W2 = (const float*)d_in[4];
    const float* b2 = (const float*)d_in[5];
    float* out = (float*)d_out;

    const int n = in_sizes[0] / DIN;
    const int E = in_sizes[1] / 2;
    const int* src = ei;
    const int* dst = ei + E;

    const int SMEM1 = 128 * LDA * 2 * 2 + 128 * LDC * 4;           // ~134 KB
    const int SMEM2 = 128 * LDA * 2 + 128 * LDB2 * 2 + 128 * LDC2 * 4;  // ~88 KB
    cudaFuncSetAttribute(k_gemm1, cudaFuncAttributeMaxDynamicSharedMemorySize, SMEM1);
    cudaFuncSetAttribute(k_gemm2, cudaFuncAttributeMaxDynamicSharedMemorySize, SMEM2);

    const int nb = (n + 1023) / 1024;

    k_zero_cnt<<<(n + 255) / 256, 256>>>(n);
    k_count<<<(E + 255) / 256, 256>>>(dst, E);
    k_dinv<<<(n + 255) / 256, 256>>>(n);
    k_scan1<<<nb, 1024>>>(n);
    k_scan2<<<1, 128>>>(nb);
    k_scan3<<<(n + 255) / 256, 256>>>(n);
    k_fill<<<(E + 255) / 256, 256>>>(src, dst, E);

    k_gemm1<<<(n + 127) / 128, 256, SMEM1>>>(x, W1, n);
    k_agg1<<<(n * 32 + 255) / 256, 256>>>(n);

    k_gemm2<<<(n + 127) / 128, 256, SMEM2>>>(W2, b1, n);
    k_agg2<<<(n * 32 + 255) / 256, 256>>>(b2, out, n);
}

// round 4
// speedup vs baseline: 2.2760x; 1.0973x over previous
#include <cuda_runtime.h>
#include <cuda_fp16.h>
#include <mma.h>
#include <cstdint>

using namespace nvcuda;

#define DIN 128
#define DH  128
#define DOUT 64
#define NMAX 100000
#define EMAX 1600000

// ---------------------------------------------------------------- scratch
__device__ __half g_h1[(size_t)NMAX * DH];     // x@W1 (unscaled), fp16
__device__ __half g_x2[(size_t)NMAX * DH];     // relu(agg1 + b1), fp16
__device__ __half g_hs2[(size_t)NMAX * DOUT];  // (x2@W2) * dinv[row], fp16
__device__ float  g_dinv[NMAX];
__device__ int    g_cnt[NMAX];
__device__ int    g_rowstart[NMAX];
__device__ int    g_cursor[NMAX];
__device__ int    g_csrc[EMAX];
__device__ int    g_bsum[128];
__device__ int    g_bpre[128];

// ---------------------------------------------------------------- degree / CSR build
__global__ void k_count(const int* __restrict__ dst, int E) {
    int e = blockIdx.x * blockDim.x + threadIdx.x;
    if (e < E) atomicAdd(&g_cnt[dst[e]], 1);
}

// block-wise exclusive scan + dinv
__global__ void __launch_bounds__(1024) k_scan1(int n) {
    __shared__ int sm[1024];
    int i = blockIdx.x * 1024 + threadIdx.x;
    int v = (i < n) ? g_cnt[i] : 0;
    if (i < n) g_dinv[i] = rsqrtf(1.0f + (float)v);
    sm[threadIdx.x] = v;
    __syncthreads();
#pragma unroll
    for (int off = 1; off < 1024; off <<= 1) {
        int t = (threadIdx.x >= off) ? sm[threadIdx.x - off] : 0;
        __syncthreads();
        sm[threadIdx.x] += t;
        __syncthreads();
    }
    int inc = sm[threadIdx.x];
    if (i < n) g_rowstart[i] = inc - v;
    if (threadIdx.x == 1023) g_bsum[blockIdx.x] = inc;
}

__global__ void __launch_bounds__(128) k_scan2(int nb) {
    __shared__ int sm[128];
    int v = (threadIdx.x < nb) ? g_bsum[threadIdx.x] : 0;
    sm[threadIdx.x] = v;
    __syncthreads();
#pragma unroll
    for (int off = 1; off < 128; off <<= 1) {
        int t = (threadIdx.x >= off) ? sm[threadIdx.x - off] : 0;
        __syncthreads();
        sm[threadIdx.x] += t;
        __syncthreads();
    }
    g_bpre[threadIdx.x] = sm[threadIdx.x] - v;
}

__global__ void k_scan3(int n) {
    int i = blockIdx.x * blockDim.x + threadIdx.x;
    if (i < n) {
        int rs = g_rowstart[i] + g_bpre[i >> 10];
        g_rowstart[i] = rs;
        g_cursor[i] = rs;
    }
}

__global__ void k_fill(const int* __restrict__ src, const int* __restrict__ dst, int E) {
    int e = blockIdx.x * blockDim.x + threadIdx.x;
    if (e < E) {
        int p = atomicAdd(&g_cursor[dst[e]], 1);
        g_csrc[p] = src[e];
    }
}

// ---------------------------------------------------------------- GEMM1 (wmma fp16)
// h1 = x @ W1 (unscaled), output fp16. Tile 128x128, 8 warps.
#define LDA 136   // half, padded
#define LDC 132   // float, padded
__global__ void __launch_bounds__(256) k_gemm1(const float* __restrict__ x,
                                               const float* __restrict__ W1,
                                               int n) {
    extern __shared__ char smraw[];
    __half* Ah = (__half*)smraw;                       // [128][136]
    __half* Bh = Ah + 128 * LDA;                       // [128][136]
    float*  Cf = (float*)(Bh + 128 * LDA);             // [128][132]

    const int tid = threadIdx.x;
    const int row0 = blockIdx.x * 128;

    const float4* x4 = (const float4*)x;
#pragma unroll
    for (int i = 0; i < 16; i++) {
        int idx = tid + 256 * i;
        int r = idx >> 5, c4 = idx & 31;
        float4 v = make_float4(0.f, 0.f, 0.f, 0.f);
        if (row0 + r < n) v = x4[(size_t)(row0 + r) * 32 + c4];
        __half2* p = (__half2*)&Ah[r * LDA + c4 * 4];
        p[0] = __floats2half2_rn(v.x, v.y);
        p[1] = __floats2half2_rn(v.z, v.w);
    }
    const float4* W4 = (const float4*)W1;
#pragma unroll
    for (int i = 0; i < 16; i++) {
        int idx = tid + 256 * i;
        int r = idx >> 5, c4 = idx & 31;
        float4 v = W4[idx];
        __half2* p = (__half2*)&Bh[r * LDA + c4 * 4];
        p[0] = __floats2half2_rn(v.x, v.y);
        p[1] = __floats2half2_rn(v.z, v.w);
    }
    __syncthreads();

    const int wid = tid >> 5;
    const int wr = (wid >> 1) * 32;
    const int wc = (wid & 1) * 64;

    wmma::fragment<wmma::accumulator, 16, 16, 16, float> cf[2][4];
#pragma unroll
    for (int i = 0; i < 2; i++)
#pragma unroll
        for (int j = 0; j < 4; j++) wmma::fill_fragment(cf[i][j], 0.f);

#pragma unroll
    for (int k = 0; k < 8; k++) {
        wmma::fragment<wmma::matrix_a, 16, 16, 16, __half, wmma::row_major> af[2];
#pragma unroll
        for (int i = 0; i < 2; i++)
            wmma::load_matrix_sync(af[i], &Ah[(wr + 16 * i) * LDA + 16 * k], LDA);
#pragma unroll
        for (int j = 0; j < 4; j++) {
            wmma::fragment<wmma::matrix_b, 16, 16, 16, __half, wmma::row_major> bf;
            wmma::load_matrix_sync(bf, &Bh[16 * k * LDA + wc + 16 * j], LDA);
#pragma unroll
            for (int i = 0; i < 2; i++)
                wmma::mma_sync(cf[i][j], af[i], bf, cf[i][j]);
        }
    }

#pragma unroll
    for (int i = 0; i < 2; i++)
#pragma unroll
        for (int j = 0; j < 4; j++)
            wmma::store_matrix_sync(&Cf[(wr + 16 * i) * LDC + wc + 16 * j],
                                    cf[i][j], LDC, wmma::mem_row_major);
    __syncthreads();

#pragma unroll
    for (int i = 0; i < 16; i++) {
        int idx = tid + 256 * i;
        int r = idx >> 5, c4 = idx & 31;
        int gr = row0 + r;
        if (gr < n) {
            float* c = &Cf[r * LDC + c4 * 4];
            __half2 h0 = __floats2half2_rn(c[0], c[1]);
            __half2 h1 = __floats2half2_rn(c[2], c[3]);
            __half2* o = (__half2*)&g_h1[(size_t)gr * DH + c4 * 4];
            o[0] = h0; o[1] = h1;
        }
    }
}

// ---------------------------------------------------------------- agg layer 1
// x2[d] = relu(dinv[d] * (h1[d]*dinv[d] + sum_s h1[s]*dinv[s]) + b1), fp16 out.
// Warp per node; gather batched 8-wide for MLP.
__global__ void __launch_bounds__(256) k_agg1(const float* __restrict__ b1, int n) {
    int w = (blockIdx.x * 256 + threadIdx.x) >> 5;
    if (w >= n) return;
    int lane = threadIdx.x & 31;
    const uint2* hs = (const uint2*)g_h1;

    float dvd = g_dinv[w];
    uint2 sv = hs[(size_t)w * 32 + lane];
    __half2 a01 = *(__half2*)&sv.x, a23 = *(__half2*)&sv.y;
    float2 f01 = __half22float2(a01), f23 = __half22float2(a23);
    float4 acc = make_float4(f01.x * dvd, f01.y * dvd, f23.x * dvd, f23.y * dvd);

    int start = g_rowstart[w];
    int end = start + g_cnt[w];
    for (int base = start; base < end; base += 32) {
        int idx = base + lane;
        int s = (idx < end) ? __ldg(&g_csrc[idx]) : 0;
        int m = min(32, end - base);
        int k = 0;
        for (; k + 8 <= m; k += 8) {
            int ss[8]; uint2 vv[8]; float dd[8];
#pragma unroll
            for (int j = 0; j < 8; j++) ss[j] = __shfl_sync(0xffffffffu, s, k + j);
#pragma unroll
            for (int j = 0; j < 8; j++) vv[j] = hs[(size_t)ss[j] * 32 + lane];
#pragma unroll
            for (int j = 0; j < 8; j++) dd[j] = __ldg(&g_dinv[ss[j]]);
#pragma unroll
            for (int j = 0; j < 8; j++) {
                float2 l01 = __half22float2(*(__half2*)&vv[j].x);
                float2 l23 = __half22float2(*(__half2*)&vv[j].y);
                acc.x = fmaf(l01.x, dd[j], acc.x);
                acc.y = fmaf(l01.y, dd[j], acc.y);
                acc.z = fmaf(l23.x, dd[j], acc.z);
                acc.w = fmaf(l23.y, dd[j], acc.w);
            }
        }
        for (; k < m; k++) {
            int ss = __shfl_sync(0xffffffffu, s, k);
            uint2 v = hs[(size_t)ss * 32 + lane];
            float dd = __ldg(&g_dinv[ss]);
            float2 l01 = __half22float2(*(__half2*)&v.x);
            float2 l23 = __half22float2(*(__half2*)&v.y);
            acc.x = fmaf(l01.x, dd, acc.x);
            acc.y = fmaf(l01.y, dd, acc.y);
            acc.z = fmaf(l23.x, dd, acc.z);
            acc.w = fmaf(l23.y, dd, acc.w);
        }
    }
    float4 bb = __ldg(&((const float4*)b1)[lane]);
    float ox = fmaxf(acc.x * dvd + bb.x, 0.f);
    float oy = fmaxf(acc.y * dvd + bb.y, 0.f);
    float oz = fmaxf(acc.z * dvd + bb.z, 0.f);
    float ow = fmaxf(acc.w * dvd + bb.w, 0.f);
    uint2 ov;
    *(__half2*)&ov.x = __floats2half2_rn(ox, oy);
    *(__half2*)&ov.y = __floats2half2_rn(oz, ow);
    ((uint2*)g_x2)[(size_t)w * 32 + lane] = ov;
}

// ---------------------------------------------------------------- GEMM2 (wmma fp16)
// hs2 = (x2 @ W2) * dinv[row], fp16 out. Tile 128x64, 8 warps.
#define LDB2 72
#define LDC2 68
__global__ void __launch_bounds__(256) k_gemm2(const float* __restrict__ W2, int n) {
    extern __shared__ char smraw[];
    __half* Ah = (__half*)smraw;                       // [128][136]
    __half* Bh = Ah + 128 * LDA;                       // [128][72]
    float*  Cf = (float*)(Bh + 128 * LDB2);            // [128][68]

    const int tid = threadIdx.x;
    const int row0 = blockIdx.x * 128;

    // A = x2 tile (already fp16, relu'd + biased) — straight copy
    const uint2* x24 = (const uint2*)g_x2;
#pragma unroll
    for (int i = 0; i < 16; i++) {
        int idx = tid + 256 * i;
        int r = idx >> 5, c4 = idx & 31;
        uint2 v = make_uint2(0u, 0u);
        if (row0 + r < n) v = x24[(size_t)(row0 + r) * 32 + c4];
        *(uint2*)&Ah[r * LDA + c4 * 4] = v;
    }
    const float4* W4 = (const float4*)W2;
#pragma unroll
    for (int i = 0; i < 8; i++) {
        int idx = tid + 256 * i;
        int r = idx >> 4, c4 = idx & 15;
        float4 v = W4[idx];
        __half2* p = (__half2*)&Bh[r * LDB2 + c4 * 4];
        p[0] = __floats2half2_rn(v.x, v.y);
        p[1] = __floats2half2_rn(v.z, v.w);
    }
    __syncthreads();

    const int wid = tid >> 5;
    const int wr = wid * 16;

    wmma::fragment<wmma::accumulator, 16, 16, 16, float> cf[4];
#pragma unroll
    for (int j = 0; j < 4; j++) wmma::fill_fragment(cf[j], 0.f);

#pragma unroll
    for (int k = 0; k < 8; k++) {
        wmma::fragment<wmma::matrix_a, 16, 16, 16, __half, wmma::row_major> af;
        wmma::load_matrix_sync(af, &Ah[wr * LDA + 16 * k], LDA);
#pragma unroll
        for (int j = 0; j < 4; j++) {
            wmma::fragment<wmma::matrix_b, 16, 16, 16, __half, wmma::row_major> bf;
            wmma::load_matrix_sync(bf, &Bh[16 * k * LDB2 + 16 * j], LDB2);
            wmma::mma_sync(cf[j], af, bf, cf[j]);
        }
    }

#pragma unroll
    for (int j = 0; j < 4; j++)
        wmma::store_matrix_sync(&Cf[wr * LDC2 + 16 * j], cf[j], LDC2,
                                wmma::mem_row_major);
    __syncthreads();

#pragma unroll
    for (int i = 0; i < 8; i++) {
        int idx = tid + 256 * i;
        int r = idx >> 4, c4 = idx & 15;
        int gr = row0 + r;
        if (gr < n) {
            float dv = g_dinv[gr];
            float* c = &Cf[r * LDC2 + c4 * 4];
            __half2 h0 = __floats2half2_rn(c[0] * dv, c[1] * dv);
            __half2 h1 = __floats2half2_rn(c[2] * dv, c[3] * dv);
            __half2* o = (__half2*)&g_hs2[(size_t)gr * DOUT + c4 * 4];
            o[0] = h0; o[1] = h1;
        }
    }
}

// ---------------------------------------------------------------- agg layer 2
// out[d] = dinv[d] * (hs2[d] + sum hs2[s]) + b2.  Warp per node, 8-wide batch.
__global__ void __launch_bounds__(256) k_agg2(const float* __restrict__ b2,
                                              float* __restrict__ out, int n) {
    int w = (blockIdx.x * 256 + threadIdx.x) >> 5;
    if (w >= n) return;
    int lane = threadIdx.x & 31;
    const unsigned* hs = (const unsigned*)g_hs2;

    unsigned sv = hs[(size_t)w * 32 + lane];
    float2 acc = __half22float2(*(__half2*)&sv);

    int start = g_rowstart[w];
    int end = start + g_cnt[w];
    for (int base = start; base < end; base += 32) {
        int idx = base + lane;
        int s = (idx < end) ? __ldg(&g_csrc[idx]) : 0;
        int m = min(32, end - base);
        int k = 0;
        for (; k + 8 <= m; k += 8) {
            int ss[8]; unsigned vv[8];
#pragma unroll
            for (int j = 0; j < 8; j++) ss[j] = __shfl_sync(0xffffffffu, s, k + j);
#pragma unroll
            for (int j = 0; j < 8; j++) vv[j] = hs[(size_t)ss[j] * 32 + lane];
#pragma unroll
            for (int j = 0; j < 8; j++) {
                float2 f = __half22float2(*(__half2*)&vv[j]);
                acc.x += f.x; acc.y += f.y;
            }
        }
        for (; k < m; k++) {
            int ss = __shfl_sync(0xffffffffu, s, k);
            unsigned v = hs[(size_t)ss * 32 + lane];
            float2 f = __half22float2(*(__half2*)&v);
            acc.x += f.x; acc.y += f.y;
        }
    }
    float dv = g_dinv[w];
    float2 bb = __ldg(&((const float2*)b2)[lane]);
    float2 o = make_float2(acc.x * dv + bb.x, acc.y * dv + bb.y);
    ((float2*)out)[(size_t)w * 32 + lane] = o;
}

// ---------------------------------------------------------------- launch
extern "C" void kernel_launch(void* const* d_in, const int* in_sizes, int n_in,
                              void* d_out, int out_size) {
    const float* x  = (const float*)d_in[0];
    const int*   ei = (const int*)d_in[1];
    const float* W1 = (const float*)d_in[2];
    const float* b1 = (const float*)d_in[3];
    const float* W2 = (const float*)d_in[4];
    const float* b2 = (const float*)d_in[5];
    float* out = (float*)d_out;

    const int n = in_sizes[0] / DIN;
    const int E = in_sizes[1] / 2;
    const int* src = ei;
    const int* dst = ei + E;

    const int SMEM1 = 128 * LDA * 2 * 2 + 128 * LDC * 4;
    const int SMEM2 = 128 * LDA * 2 + 128 * LDB2 * 2 + 128 * LDC2 * 4;
    cudaFuncSetAttribute(k_gemm1, cudaFuncAttributeMaxDynamicSharedMemorySize, SMEM1);
    cudaFuncSetAttribute(k_gemm2, cudaFuncAttributeMaxDynamicSharedMemorySize, SMEM2);

    void* cnt_ptr = nullptr;
    cudaGetSymbolAddress(&cnt_ptr, g_cnt);

    const int nb = (n + 1023) / 1024;

    cudaMemsetAsync(cnt_ptr, 0, (size_t)n * sizeof(int));
    k_count<<<(E + 255) / 256, 256>>>(dst, E);
    k_scan1<<<nb, 1024>>>(n);
    k_scan2<<<1, 128>>>(nb);
    k_scan3<<<(n + 255) / 256, 256>>>(n);
    k_fill<<<(E + 255) / 256, 256>>>(src, dst, E);

    k_gemm1<<<(n + 127) / 128, 256, SMEM1>>>(x, W1, n);
    k_agg1<<<(n * 32 + 255) / 256, 256>>>(b1, n);

    k_gemm2<<<(n + 127) / 128, 256, SMEM2>>>(W2, n);
    k_agg2<<<(n * 32 + 255) / 256, 256>>>(b2, out, n);
}